// round 15
// baseline (speedup 1.0000x reference)
#include <cuda_runtime.h>
#include <cuda_bf16.h>
#include <math.h>
#include <stdint.h>

// ---------------- problem constants ----------------
#define BB 1024
#define TT 128
#define FF 128
#define HH 512
#define G4 2048            // 4*HH
#define KC 768             // 2*FF + HH
#define BTn (BB*TT)        // 131072

constexpr size_t BTFc    = (size_t)BTn * FF;
constexpr size_t OFF_IMP = 0;
constexpr size_t OFF_CH1 = BTFc;
constexpr size_t OFF_HT  = 2 * BTFc;
constexpr size_t OFF_XH  = 2 * BTFc + (size_t)BB * HH;
constexpr size_t OFF_CH2 = OFF_XH + BTFc;
constexpr size_t OFF_ZH  = OFF_CH2 + BTFc;

constexpr size_t ABUF = (size_t)BB * KC;   // one A-operand buffer (per parity)

// ---------------- device scratch (static, no allocs) ----------------
__device__ __align__(16) float g_gamma_x[(size_t)BTn * FF];   // 64 MB
__device__ __align__(16) float g_gamma_h[(size_t)BTn * HH];   // 256 MB
__device__ __align__(16) float g_alpha  [(size_t)BTn * FF];   // 64 MB
__device__ __align__(16) float g_h [BB * HH];
__device__ __align__(16) float g_c [BB * HH];
__device__ __align__(16) float g_bcat[G4];                    // gate-interleaved
__device__ __align__(16) float g_part[(size_t)BB * G4];       // 8 MB fp32 partial gates

// dependency flags (monotonic within a replay; reset by k_prep each replay)
__device__ unsigned g_fA[32];    // stepA block completion, value = t+1
__device__ unsigned g_fP[256];   // gates_partial block completion, value = t+1

// Gates A operand, bf16 split, DOUBLE-BUFFERED by step parity:
// buffer b = t&1 is read at step t; fin epilogue writes h*gamma(t+1) into 1-b.
// layout per row: [c_c(128) | m(128) | h*gamma_h(512)]
__device__ __align__(16) __nv_bfloat16 g_AH[2 * ABUF];
__device__ __align__(16) __nv_bfloat16 g_AL[2 * ABUF];

// bf16 split weights, TRANSPOSED [K][N] row-major (W_cat cols gate-interleaved n' = j*4+g)
__device__ __align__(16) __nv_bfloat16 g_WghH  [FF * HH],   g_WghL  [FF * HH];
__device__ __align__(16) __nv_bfloat16 g_WcombH[256 * FF],  g_WcombL[256 * FF];
__device__ __align__(16) __nv_bfloat16 g_WhistH[HH * FF],   g_WhistL[HH * FF];
__device__ __align__(16) __nv_bfloat16 g_WodH  [FF * FF],   g_WodL  [FF * FF];
__device__ __align__(16) __nv_bfloat16 g_WcatH[(size_t)KC * G4], g_WcatL[(size_t)KC * G4];

__device__ __forceinline__ float sigm(float x) { return 1.0f / (1.0f + expf(-x)); }

__device__ __forceinline__ void split_w(__nv_bfloat16* H, __nv_bfloat16* L, size_t i, float w) {
    __nv_bfloat16 h = __float2bfloat16(w);
    H[i] = h;
    L[i] = __float2bfloat16(w - __bfloat162float(h));
}

// ---------------- cp.async helpers ----------------
__device__ __forceinline__ void cp16(uint32_t dst, const void* src) {
    asm volatile("cp.async.cg.shared.global [%0], [%1], 16;" :: "r"(dst), "l"(src));
}
__device__ __forceinline__ void cp8(uint32_t dst, const void* src) {
    asm volatile("cp.async.ca.shared.global [%0], [%1], 8;" :: "r"(dst), "l"(src));
}
#define CP_COMMIT() asm volatile("cp.async.commit_group;" ::: "memory")
#define CP_WAIT(n)  asm volatile("cp.async.wait_group %0;" :: "n"(n) : "memory")

__device__ __forceinline__ void waitflag(const unsigned* f, unsigned want) {
    while (*(volatile const unsigned*)f < want) { __nanosleep(64); }
}

// ---------------- precompute ----------------
__global__ void k_prep(const float* __restrict__ D,    const float* __restrict__ Wgx,
                       const float* __restrict__ bgx,  const float* __restrict__ Wfeat,
                       const float* __restrict__ Wih,  const float* __restrict__ Whh,
                       const float* __restrict__ bih,  const float* __restrict__ bhh,
                       const float* __restrict__ Wgh,  const float* __restrict__ Wcomb,
                       const float* __restrict__ Whist)
{
    size_t tid    = (size_t)blockIdx.x * blockDim.x + threadIdx.x;
    size_t stride = (size_t)gridDim.x * blockDim.x;

    // reset dependency flags (required for CUDA-graph replays)
    for (size_t i = tid; i < 32;  i += stride) g_fA[i] = 0;
    for (size_t i = tid; i < 256; i += stride) g_fP[i] = 0;

    for (size_t i = tid; i < (size_t)BTn * FF; i += stride) {
        int f = (int)(i & (FF - 1));
        float v = D[i] * Wgx[f * FF + f] + bgx[f];
        g_gamma_x[i] = expf(-fmaxf(v, 0.0f));
    }
    // gate-interleaved bias: n' = j*4+g  <->  n = g*512+j
    for (size_t i = tid; i < (size_t)G4; i += stride) {
        int j = (int)(i >> 2), g = (int)(i & 3), n = g * HH + j;
        g_bcat[i] = bih[n] + bhh[n];
    }
    for (size_t i = tid; i < (size_t)BB * HH; i += stride) { g_h[i] = 0.0f; g_c[i] = 0.0f; }
    for (size_t i = tid; i < 2 * ABUF; i += stride) {
        g_AH[i] = __float2bfloat16(0.0f);
        g_AL[i] = __float2bfloat16(0.0f);
    }

    for (size_t i = tid; i < (size_t)FF * HH; i += stride) {     // W_gh^T  [K][N]
        int k = (int)(i / HH), n = (int)(i % HH);
        split_w(g_WghH, g_WghL, i, Wgh[(size_t)n * FF + k]);
    }
    for (size_t i = tid; i < (size_t)256 * FF; i += stride) {    // W_comb^T
        int k = (int)(i / FF), n = (int)(i % FF);
        split_w(g_WcombH, g_WcombL, i, Wcomb[(size_t)n * 256 + k]);
    }
    for (size_t i = tid; i < (size_t)HH * FF; i += stride) {     // W_hist^T
        int k = (int)(i / FF), n = (int)(i % FF);
        split_w(g_WhistH, g_WhistL, i, Whist[(size_t)n * HH + k]);
    }
    for (size_t i = tid; i < (size_t)FF * FF; i += stride) {     // W_feat^T off-diag
        int k = (int)(i / FF), n = (int)(i % FF);
        float w = (k == n) ? 0.0f : Wfeat[(size_t)n * FF + k];
        split_w(g_WodH, g_WodL, i, w);
    }
    // W_cat^T [K][N'], gate-interleaved columns
    for (size_t i = tid; i < (size_t)KC * G4; i += stride) {
        int k = (int)(i / G4), np = (int)(i % G4);
        int j = np >> 2, g = np & 3, n = g * HH + j;
        float w = (k < 2 * FF) ? Wih[(size_t)n * (2 * FF) + k]
                               : Whh[(size_t)n * HH + (k - 2 * FF)];
        split_w(g_WcatH, g_WcatL, i, w);
    }
}

// ---------------- mma.sync helpers ----------------
__device__ __forceinline__ void ldmA(uint32_t* r, const __nv_bfloat16* p) {
    uint32_t a = (uint32_t)__cvta_generic_to_shared(p);
    asm volatile("ldmatrix.sync.aligned.m8n8.x4.shared.b16 {%0,%1,%2,%3}, [%4];"
                 : "=r"(r[0]), "=r"(r[1]), "=r"(r[2]), "=r"(r[3]) : "r"(a));
}
__device__ __forceinline__ void ldmBT(uint32_t* r, const __nv_bfloat16* p) {
    uint32_t a = (uint32_t)__cvta_generic_to_shared(p);
    asm volatile("ldmatrix.sync.aligned.m8n8.x4.trans.shared.b16 {%0,%1,%2,%3}, [%4];"
                 : "=r"(r[0]), "=r"(r[1]), "=r"(r[2]), "=r"(r[3]) : "r"(a));
}
__device__ __forceinline__ void mma16816(float* d, const uint32_t* a, const uint32_t* b) {
    asm volatile("mma.sync.aligned.m16n8k16.row.col.f32.bf16.bf16.f32 "
                 "{%0,%1,%2,%3}, {%4,%5,%6,%7}, {%8,%9}, {%0,%1,%2,%3};"
                 : "+f"(d[0]), "+f"(d[1]), "+f"(d[2]), "+f"(d[3])
                 : "r"(a[0]), "r"(a[1]), "r"(a[2]), "r"(a[3]), "r"(b[0]), "r"(b[1]));
}
__device__ __forceinline__ void splitA_store(__nv_bfloat16* pH, __nv_bfloat16* pL, float4 a) {
    __nv_bfloat16 h0 = __float2bfloat16(a.x), h1 = __float2bfloat16(a.y);
    __nv_bfloat16 h2 = __float2bfloat16(a.z), h3 = __float2bfloat16(a.w);
    __nv_bfloat16 l0 = __float2bfloat16(a.x - __bfloat162float(h0));
    __nv_bfloat16 l1 = __float2bfloat16(a.y - __bfloat162float(h1));
    __nv_bfloat16 l2 = __float2bfloat16(a.z - __bfloat162float(h2));
    __nv_bfloat16 l3 = __float2bfloat16(a.w - __bfloat162float(h3));
    ((__nv_bfloat162*)pH)[0] = __halves2bfloat162(h0, h1);
    ((__nv_bfloat162*)pH)[1] = __halves2bfloat162(h2, h3);
    ((__nv_bfloat162*)pL)[0] = __halves2bfloat162(l0, l1);
    ((__nv_bfloat162*)pL)[1] = __halves2bfloat162(l2, l3);
}
__device__ __forceinline__ void split_scalar(__nv_bfloat16* pH, __nv_bfloat16* pL, float v) {
    __nv_bfloat16 h = __float2bfloat16(v);
    *pH = h;
    *pL = __float2bfloat16(v - __bfloat162float(h));
}

// ============================================================================
// Precompute GEMMs (parallel over B*T): GH and ALPHA (proven R5 code)
// ============================================================================
enum Mode { M_GH = 0, M_ALPHA = 1 };

template <int MODE>
__device__ __forceinline__ float4 loadApre(int row, int k, const float* __restrict__ Mm,
                                           const float* __restrict__ D)
{
    if (MODE == M_GH) {
        return *(const float4*)(D + (size_t)row * FF + k);
    } else {
        if (k < FF) return *(const float4*)(g_gamma_x + (size_t)row * FF + k);
        return *(const float4*)(Mm + (size_t)row * FF + (k - FF));
    }
}

template <int MODE>
__global__ __launch_bounds__(256)
void k_mma(const float* __restrict__ Mm, const float* __restrict__ D,
           const float* __restrict__ bias)
{
    constexpr int KD = (MODE == M_GH) ? FF : 2 * FF;
    constexpr int ND = (MODE == M_GH) ? HH : FF;
    constexpr int BM = 64, BN = 128;
    constexpr int LDA = 40, LDB = BN + 8;

    const __nv_bfloat16* WH = (MODE == M_GH) ? g_WghH : g_WcombH;
    const __nv_bfloat16* WL = (MODE == M_GH) ? g_WghL : g_WcombL;

    __shared__ __align__(16) __nv_bfloat16 AsH[BM * LDA], AsL[BM * LDA];
    __shared__ __align__(16) __nv_bfloat16 BsH[32 * LDB], BsL[32 * LDB];

    const int tid = threadIdx.x, lane = tid & 31, w = tid >> 5;
    const int wm = w >> 2, wn = w & 3;
    const int m0 = blockIdx.x * BM, n0 = blockIdx.y * BN;
    const int mA = tid >> 2, kA = (tid & 3) * 4;
    const int lr = lane & 15, lc = (lane >> 4) * 8;

    float acc[2][4][4];
    #pragma unroll
    for (int i = 0; i < 2; i++) for (int nb = 0; nb < 4; nb++) for (int e = 0; e < 4; e++)
        acc[i][nb][e] = 0.0f;

    for (int kt = 0; kt < KD; kt += 32) {
        float4 a1 = loadApre<MODE>(m0 + mA, kt + kA,      Mm, D);
        float4 a2 = loadApre<MODE>(m0 + mA, kt + kA + 16, Mm, D);
        uint4 bqh[2], bql[2];
        #pragma unroll
        for (int q = 0; q < 2; q++) {
            int cidx = q * 256 + tid;
            int row = cidx >> 4, col = (cidx & 15) * 8;
            size_t gi = (size_t)(kt + row) * ND + n0 + col;
            bqh[q] = *(const uint4*)(WH + gi);
            bql[q] = *(const uint4*)(WL + gi);
        }
        __syncthreads();
        splitA_store(&AsH[mA * LDA + kA],      &AsL[mA * LDA + kA],      a1);
        splitA_store(&AsH[mA * LDA + kA + 16], &AsL[mA * LDA + kA + 16], a2);
        #pragma unroll
        for (int q = 0; q < 2; q++) {
            int cidx = q * 256 + tid;
            int row = cidx >> 4, col = (cidx & 15) * 8;
            *(uint4*)&BsH[row * LDB + col] = bqh[q];
            *(uint4*)&BsL[row * LDB + col] = bql[q];
        }
        __syncthreads();
        #pragma unroll
        for (int kk = 0; kk < 32; kk += 16) {
            uint32_t ah[2][4], al[2][4];
            #pragma unroll
            for (int i = 0; i < 2; i++) {
                const int rowb = wm * 32 + i * 16 + lr;
                ldmA(ah[i], &AsH[rowb * LDA + kk + lc]);
                ldmA(al[i], &AsL[rowb * LDA + kk + lc]);
            }
            uint32_t bh[4][2], bl[4][2];
            #pragma unroll
            for (int g = 0; g < 2; g++) {
                uint32_t r4[4];
                const int coff = wn * 32 + g * 16 + lc;
                ldmBT(r4, &BsH[(kk + lr) * LDB + coff]);
                bh[2*g][0] = r4[0]; bh[2*g][1] = r4[1];
                bh[2*g+1][0] = r4[2]; bh[2*g+1][1] = r4[3];
                ldmBT(r4, &BsL[(kk + lr) * LDB + coff]);
                bl[2*g][0] = r4[0]; bl[2*g][1] = r4[1];
                bl[2*g+1][0] = r4[2]; bl[2*g+1][1] = r4[3];
            }
            #pragma unroll
            for (int i = 0; i < 2; i++)
                #pragma unroll
                for (int nb = 0; nb < 4; nb++) {
                    mma16816(acc[i][nb], ah[i], bh[nb]);
                    mma16816(acc[i][nb], al[i], bh[nb]);
                    mma16816(acc[i][nb], ah[i], bl[nb]);
                }
        }
    }
    #pragma unroll
    for (int i = 0; i < 2; i++)
        #pragma unroll
        for (int nb = 0; nb < 4; nb++) {
            const int rbase = m0 + wm * 32 + i * 16 + (lane >> 2);
            const int cbase = n0 + wn * 32 + nb * 8 + (lane & 3) * 2;
            #pragma unroll
            for (int e = 0; e < 4; e++) {
                const int r = rbase + (e >> 1) * 8;
                const int c = cbase + (e & 1);
                float v = acc[i][nb][e] + bias[c];
                if (MODE == M_GH) g_gamma_h[(size_t)r * HH + c] = expf(-fmaxf(v, 0.0f));
                else              g_alpha  [(size_t)r * FF + c] = sigm(v);
            }
        }
}

// ============================================================================
// Shared gates mainloop: 64x128 tile, 2-stage cp.async, K chunks of 32
// smem per stage (27648 bytes): AsH 5120 | AsL 5120 | BsH 8704 | BsL 8704
// ============================================================================
template <int KT0, int NCH>
__device__ __forceinline__ void gates_loop(char* sm, size_t ab, int m0, int n0,
                                           float (&acc)[2][4][4])
{
    const uint32_t smb = (uint32_t)__cvta_generic_to_shared(sm);
    constexpr int LDA = 40, LDB = 136, STG = 27648;
    const int tid = threadIdx.x, lane = tid & 31, w = tid >> 5;
    const int wm = w >> 2, wnq = w & 3;
    const int arow = tid >> 2, akq = (tid & 3) * 8;
    const int lr = lane & 15, lc = (lane >> 4) * 8;
    const int brow0 = tid >> 4, bcol0 = (tid & 15) * 8;
    const int brow1 = (256 + tid) >> 4;

    auto issueG = [&](int kt, int s) {
        const size_t ga = ab + (size_t)(m0 + arow) * KC + kt + akq;
        uint32_t base = smb + s * STG;
        uint32_t da = base + (arow * LDA + akq) * 2;
        cp16(da,        g_AH + ga);
        cp16(da + 5120, g_AL + ga);
        uint32_t bb = base + 10240;
        size_t gi0 = (size_t)(kt + brow0) * G4 + n0 + bcol0;
        size_t gi1 = (size_t)(kt + brow1) * G4 + n0 + bcol0;
        cp16(bb + (brow0 * LDB + bcol0) * 2,        g_WcatH + gi0);
        cp16(bb + (brow1 * LDB + bcol0) * 2,        g_WcatH + gi1);
        cp16(bb + 8704 + (brow0 * LDB + bcol0) * 2, g_WcatL + gi0);
        cp16(bb + 8704 + (brow1 * LDB + bcol0) * 2, g_WcatL + gi1);
    };

    issueG(KT0, 0); CP_COMMIT();

    #pragma unroll 1
    for (int c = 0; c < NCH; c++) {
        if (c + 1 < NCH) issueG(KT0 + (c + 1) * 32, (c + 1) & 1);
        CP_COMMIT();
        CP_WAIT(1);
        __syncthreads();
        const int s = c & 1;
        const __nv_bfloat16* AsH = (const __nv_bfloat16*)(sm + s * STG);
        const __nv_bfloat16* AsL = (const __nv_bfloat16*)(sm + s * STG + 5120);
        const __nv_bfloat16* BsH = (const __nv_bfloat16*)(sm + s * STG + 10240);
        const __nv_bfloat16* BsL = (const __nv_bfloat16*)(sm + s * STG + 18944);
        #pragma unroll
        for (int kk = 0; kk < 32; kk += 16) {
            uint32_t ah[2][4], al[2][4];
            #pragma unroll
            for (int i = 0; i < 2; i++) {
                const int rowb = wm * 32 + i * 16 + lr;
                ldmA(ah[i], &AsH[rowb * LDA + kk + lc]);
                ldmA(al[i], &AsL[rowb * LDA + kk + lc]);
            }
            uint32_t bh[4][2], bl[4][2];
            #pragma unroll
            for (int g = 0; g < 2; g++) {
                uint32_t r4[4];
                const int coff = wnq * 32 + g * 16 + lc;
                ldmBT(r4, &BsH[(kk + lr) * LDB + coff]);
                bh[2*g][0] = r4[0]; bh[2*g][1] = r4[1];
                bh[2*g+1][0] = r4[2]; bh[2*g+1][1] = r4[3];
                ldmBT(r4, &BsL[(kk + lr) * LDB + coff]);
                bl[2*g][0] = r4[0]; bl[2*g][1] = r4[1];
                bl[2*g+1][0] = r4[2]; bl[2*g+1][1] = r4[3];
            }
            #pragma unroll
            for (int i = 0; i < 2; i++)
                #pragma unroll
                for (int nb = 0; nb < 4; nb++) {
                    mma16816(acc[i][nb], ah[i], bh[nb]);
                    mma16816(acc[i][nb], al[i], bh[nb]);
                    mma16816(acc[i][nb], ah[i], bl[nb]);
                }
        }
        __syncthreads();
    }
}

// ============================================================================
// stepA body: fused XH (K=512, 3-stage) + ZH (K=128, 2-stage). BM=32.
// smem: A stages(3) s*5120 | B stages(3) 15360+s*17408 |
//       xcH 67584(8704) | xcL 76288(8704) | xhS 84992(16384) -> 101376
// ============================================================================
__device__ void stepA_body(int blk, int t, const float* __restrict__ X,
                           const float* __restrict__ Mm,
                           const float* __restrict__ bh_, const float* __restrict__ bf_,
                           float* __restrict__ outp, char* sm)
{
    const uint32_t smb = (uint32_t)__cvta_generic_to_shared(sm);
    __nv_bfloat16* xcH = (__nv_bfloat16*)(sm + 67584);
    __nv_bfloat16* xcL = (__nv_bfloat16*)(sm + 76288);
    float*         xhS = (float*)(sm + 84992);
    constexpr int LDA = 40, LDB = 136, LDX = 136;

    const size_t ab = (size_t)(t & 1) * ABUF;

    const int tid = threadIdx.x, lane = tid & 31, w = tid >> 5;
    const int wm = w >> 2, wn = w & 3;                 // 2x4 warps, warp tile 16x32
    const int m0 = blk * 32;
    const int arow = tid >> 3, akq = (tid & 7) * 4;
    const int lr = lane & 15, lc = (lane >> 4) * 8;
    const int brow0 = tid >> 4,          bcol0 = (tid & 15) * 8;
    const int brow1 = (256 + tid) >> 4;

    float acc[4][4];
    #pragma unroll
    for (int nb = 0; nb < 4; nb++) for (int e = 0; e < 4; e++) acc[nb][e] = 0.0f;

    auto issueXH = [&](int kt, int s) {
        const size_t ga = ab + (size_t)(m0 + arow) * KC + 256 + kt + akq;
        uint32_t da = smb + s * 5120 + (arow * LDA + akq) * 2;
        cp8(da,        g_AH + ga);
        cp8(da + 2560, g_AL + ga);
        uint32_t bb = smb + 15360 + s * 17408;
        size_t gi0 = (size_t)(kt + brow0) * FF + bcol0;
        size_t gi1 = (size_t)(kt + brow1) * FF + bcol0;
        cp16(bb + (brow0 * LDB + bcol0) * 2,        g_WhistH + gi0);
        cp16(bb + (brow1 * LDB + bcol0) * 2,        g_WhistH + gi1);
        cp16(bb + 8704 + (brow0 * LDB + bcol0) * 2, g_WhistL + gi0);
        cp16(bb + 8704 + (brow1 * LDB + bcol0) * 2, g_WhistL + gi1);
    };

    issueXH(0, 0);  CP_COMMIT();
    issueXH(32, 1); CP_COMMIT();

    #pragma unroll 1
    for (int c = 0; c < 16; c++) {
        if (c + 2 < 16) issueXH((c + 2) * 32, (c + 2) % 3);
        CP_COMMIT();
        CP_WAIT(2);
        __syncthreads();
        const int s = c % 3;
        const __nv_bfloat16* AsH = (const __nv_bfloat16*)(sm + s * 5120);
        const __nv_bfloat16* AsL = (const __nv_bfloat16*)(sm + s * 5120 + 2560);
        const __nv_bfloat16* BsH = (const __nv_bfloat16*)(sm + 15360 + s * 17408);
        const __nv_bfloat16* BsL = (const __nv_bfloat16*)(sm + 15360 + s * 17408 + 8704);
        #pragma unroll
        for (int kk = 0; kk < 32; kk += 16) {
            uint32_t ah[4], al[4];
            const int rowb = wm * 16 + lr;
            ldmA(ah, &AsH[rowb * LDA + kk + lc]);
            ldmA(al, &AsL[rowb * LDA + kk + lc]);
            uint32_t bh[4][2], bl[4][2];
            #pragma unroll
            for (int g = 0; g < 2; g++) {
                uint32_t r4[4];
                const int coff = wn * 32 + g * 16 + lc;
                ldmBT(r4, &BsH[(kk + lr) * LDB + coff]);
                bh[2*g][0] = r4[0]; bh[2*g][1] = r4[1];
                bh[2*g+1][0] = r4[2]; bh[2*g+1][1] = r4[3];
                ldmBT(r4, &BsL[(kk + lr) * LDB + coff]);
                bl[2*g][0] = r4[0]; bl[2*g][1] = r4[1];
                bl[2*g+1][0] = r4[2]; bl[2*g+1][1] = r4[3];
            }
            #pragma unroll
            for (int nb = 0; nb < 4; nb++) {
                mma16816(acc[nb], ah, bh[nb]);
                mma16816(acc[nb], al, bh[nb]);
                mma16816(acc[nb], ah, bl[nb]);
            }
        }
        __syncthreads();
    }

    // XH epilogue -> xh smem (fp32), xc smem (bf16 split), outp XH
    #pragma unroll
    for (int nb = 0; nb < 4; nb++) {
        const int rl0 = wm * 16 + (lane >> 2);
        const int c0  = wn * 32 + nb * 8 + (lane & 3) * 2;
        #pragma unroll
        for (int e = 0; e < 4; e++) {
            const int rl = rl0 + (e >> 1) * 8;
            const int c  = c0 + (e & 1);
            const int r  = m0 + rl;
            float v = acc[nb][e] + bh_[c];
            size_t idx = ((size_t)r * TT + t) * FF + c;
            outp[OFF_XH + idx] = v;
            xhS[rl * FF + c] = v;
            float mm = Mm[idx], xx = X[idx];
            float xc = mm * xx + (1.0f - mm) * v;
            split_scalar(&xcH[rl * LDX + c], &xcL[rl * LDX + c], xc);
        }
    }

    // ---- ZH: z_h = x_c @ Wod^T, K=128, 2-stage (B only) ----
    float accz[4][4];
    #pragma unroll
    for (int nb = 0; nb < 4; nb++) for (int e = 0; e < 4; e++) accz[nb][e] = 0.0f;

    auto issueZH = [&](int kt, int s) {
        uint32_t bb = smb + 15360 + s * 17408;
        size_t gi0 = (size_t)(kt + brow0) * FF + bcol0;
        size_t gi1 = (size_t)(kt + brow1) * FF + bcol0;
        cp16(bb + (brow0 * LDB + bcol0) * 2,        g_WodH + gi0);
        cp16(bb + (brow1 * LDB + bcol0) * 2,        g_WodH + gi1);
        cp16(bb + 8704 + (brow0 * LDB + bcol0) * 2, g_WodL + gi0);
        cp16(bb + 8704 + (brow1 * LDB + bcol0) * 2, g_WodL + gi1);
    };

    issueZH(0, 0); CP_COMMIT();

    #pragma unroll 1
    for (int c = 0; c < 4; c++) {
        if (c + 1 < 4) issueZH((c + 1) * 32, (c + 1) & 1);
        CP_COMMIT();
        CP_WAIT(1);
        __syncthreads();
        const int s = c & 1;
        const __nv_bfloat16* BsH = (const __nv_bfloat16*)(sm + 15360 + s * 17408);
        const __nv_bfloat16* BsL = (const __nv_bfloat16*)(sm + 15360 + s * 17408 + 8704);
        const int kt = c * 32;
        #pragma unroll
        for (int kk = 0; kk < 32; kk += 16) {
            uint32_t ah[4], al[4];
            const int rowb = wm * 16 + lr;
            ldmA(ah, &xcH[rowb * LDX + kt + kk + lc]);
            ldmA(al, &xcL[rowb * LDX + kt + kk + lc]);
            uint32_t bh[4][2], bl[4][2];
            #pragma unroll
            for (int g = 0; g < 2; g++) {
                uint32_t r4[4];
                const int coff = wn * 32 + g * 16 + lc;
                ldmBT(r4, &BsH[(kk + lr) * LDB + coff]);
                bh[2*g][0] = r4[0]; bh[2*g][1] = r4[1];
                bh[2*g+1][0] = r4[2]; bh[2*g+1][1] = r4[3];
                ldmBT(r4, &BsL[(kk + lr) * LDB + coff]);
                bl[2*g][0] = r4[0]; bl[2*g][1] = r4[1];
                bl[2*g+1][0] = r4[2]; bl[2*g+1][1] = r4[3];
            }
            #pragma unroll
            for (int nb = 0; nb < 4; nb++) {
                mma16816(accz[nb], ah, bh[nb]);
                mma16816(accz[nb], al, bh[nb]);
                mma16816(accz[nb], ah, bl[nb]);
            }
        }
        __syncthreads();
    }

    // ZH epilogue
    #pragma unroll
    for (int nb = 0; nb < 4; nb++) {
        const int rl0 = wm * 16 + (lane >> 2);
        const int c0  = wn * 32 + nb * 8 + (lane & 3) * 2;
        #pragma unroll
        for (int e = 0; e < 4; e++) {
            const int rl = rl0 + (e >> 1) * 8;
            const int c  = c0 + (e & 1);
            const int r  = m0 + rl;
            float v = accz[nb][e] + bf_[c];
            size_t idx = ((size_t)r * TT + t) * FF + c;
            float al2 = g_alpha[idx];
            float xh  = xhS[rl * FF + c];
            float ch  = al2 * v + (1.0f - al2) * xh;
            float mm  = Mm[idx], xx = X[idx];
            float cc  = mm * xx + (1.0f - mm) * ch;
            outp[OFF_ZH  + idx] = v;
            outp[OFF_CH1 + idx] = ch;
            outp[OFF_CH2 + idx] = ch;
            outp[OFF_IMP + idx] = cc;
            size_t abase = ab + (size_t)r * KC;
            split_scalar(&g_AH[abase + c], &g_AL[abase + c], cc);
            g_AH[abase + 128 + c] = __float2bfloat16(mm);
            g_AL[abase + 128 + c] = __float2bfloat16(0.0f);
        }
    }
}

// ============================================================================
// k_step: ONE launch per timestep, grid 544.
//   blocks [0,32):    stepA (BM=32)                -> flags g_fA
//   blocks [32,288):  gates_partial (K=[256,768))  -> flags g_fP
//   blocks [288,544): fin (K=[0,256) + partial + bias + LSTM); waits on flags.
// Deadlock-free: producers (lower bids) never wait; scheduler issues bids in
// order so producers always occupy slots before later fin bids.
// fin A-tile loads use cp.async.cg (L1-bypass) -> coherent with producer fences.
// ============================================================================
#define STEP_SMEM 101376

__global__ __launch_bounds__(256, 2)
void k_step(int t, const float* __restrict__ X, const float* __restrict__ Mm,
            const float* __restrict__ bh_, const float* __restrict__ bf_,
            float* __restrict__ outp)
{
    extern __shared__ __align__(16) char sm[];
    const int bid = blockIdx.x;
    const int tid = threadIdx.x;
    const size_t ab = (size_t)(t & 1) * ABUF;

    if (bid < 32) {
        // ---- role: stepA ----
        stepA_body(bid, t, X, Mm, bh_, bf_, outp, sm);
        __threadfence();
        __syncthreads();
        if (tid == 0) atomicExch(&g_fA[bid], (unsigned)(t + 1));
        return;
    }

    if (bid < 288) {
        // ---- role: gates_partial, K = [256,768) ----
        const int gb = bid - 32;
        const int m0 = (gb >> 4) * 64, n0 = (gb & 15) * 128;
        const int lane = tid & 31, w = tid >> 5;
        const int wm = w >> 2, wnq = w & 3;

        float acc[2][4][4];
        #pragma unroll
        for (int i = 0; i < 2; i++) for (int nb = 0; nb < 4; nb++) for (int e = 0; e < 4; e++)
            acc[i][nb][e] = 0.0f;

        gates_loop<256, 16>(sm, ab, m0, n0, acc);

        #pragma unroll
        for (int i = 0; i < 2; i++)
            #pragma unroll
            for (int nb = 0; nb < 4; nb++) {
                const int rl0 = wm * 32 + i * 16 + (lane >> 2);
                const int cl0 = wnq * 32 + nb * 8 + (lane & 3) * 2;
                #pragma unroll
                for (int e = 0; e < 4; e++) {
                    const int r  = m0 + rl0 + (e >> 1) * 8;
                    const int cl = cl0 + (e & 1);
                    g_part[(size_t)r * G4 + n0 + cl] = acc[i][nb][e];
                }
            }
        __threadfence();
        __syncthreads();
        if (tid == 0) atomicExch(&g_fP[gb], (unsigned)(t + 1));
        return;
    }

    // ---- role: fin ----
    const int fb = bid - 288;
    const int bx = fb >> 4, by = fb & 15;
    const int m0 = bx * 64, n0 = by * 128;
    const size_t aw = (size_t)((t + 1) & 1) * ABUF;

    if (tid == 0) {
        const unsigned want = (unsigned)(t + 1);
        waitflag(&g_fA[2 * bx],     want);
        waitflag(&g_fA[2 * bx + 1], want);
        waitflag(&g_fP[fb],         want);
    }
    __syncthreads();
    __threadfence();   // acquire-ish: order subsequent reads after flag observation

    float* sg = (float*)sm;
    constexpr int LDS_G = 132;
    const int lane = tid & 31, w = tid >> 5;
    const int wm = w >> 2, wnq = w & 3;

    float acc[2][4][4];
    #pragma unroll
    for (int i = 0; i < 2; i++) for (int nb = 0; nb < 4; nb++) for (int e = 0; e < 4; e++)
        acc[i][nb][e] = 0.0f;

    gates_loop<0, 8>(sm, ab, m0, n0, acc);

    // add partial + bias, stage into smem overlay
    #pragma unroll
    for (int i = 0; i < 2; i++)
        #pragma unroll
        for (int nb = 0; nb < 4; nb++) {
            const int rl0 = wm * 32 + i * 16 + (lane >> 2);
            const int cl0 = wnq * 32 + nb * 8 + (lane & 3) * 2;
            #pragma unroll
            for (int e = 0; e < 4; e++) {
                const int rl = rl0 + (e >> 1) * 8;
                const int cl = cl0 + (e & 1);
                sg[rl * LDS_G + cl] = acc[i][nb][e]
                                    + g_part[(size_t)(m0 + rl) * G4 + n0 + cl]
                                    + g_bcat[n0 + cl];
            }
        }
    __syncthreads();

    // fused LSTM update: tile owns rows [m0,m0+64) x j in [n0/4, n0/4+32)
    const int j0 = n0 >> 2;
    for (int idx = tid; idx < 64 * 32; idx += 256) {
        const int rl = idx >> 5, jj = idx & 31;
        const float* gb2 = sg + rl * LDS_G + jj * 4;
        float ig = sigm(gb2[0]);
        float fg = sigm(gb2[1]);
        float gg = tanhf(gb2[2]);
        float og = sigm(gb2[3]);
        const int r = m0 + rl, j = j0 + jj;
        size_t hi = (size_t)r * HH + j;
        float cnew = fg * g_c[hi] + ig * gg;
        g_c[hi] = cnew;
        float hnew = og * tanhf(cnew);
        g_h[hi] = hnew;
        if (t + 1 < TT) {
            float gam = g_gamma_h[((size_t)r * TT + t + 1) * HH + j];
            split_scalar(&g_AH[aw + (size_t)r * KC + 256 + j],
                         &g_AL[aw + (size_t)r * KC + 256 + j], hnew * gam);
        }
    }
}

__global__ void k_hT(float* __restrict__ outp)
{
    int i = blockIdx.x * blockDim.x + threadIdx.x;
    if (i < BB * HH) outp[OFF_HT + i] = g_h[i];
}

// ---------------- launch ----------------
extern "C" void kernel_launch(void* const* d_in, const int* in_sizes, int n_in,
                              void* d_out, int out_size)
{
    const float* X      = (const float*)d_in[0];
    const float* Mm     = (const float*)d_in[1];
    const float* D      = (const float*)d_in[2];
    const float* W_gh   = (const float*)d_in[3];
    const float* b_gh   = (const float*)d_in[4];
    const float* W_gx   = (const float*)d_in[5];
    const float* b_gx   = (const float*)d_in[6];
    const float* W_hist = (const float*)d_in[7];
    const float* b_hist = (const float*)d_in[8];
    const float* W_feat = (const float*)d_in[9];
    const float* b_feat = (const float*)d_in[10];
    const float* W_comb = (const float*)d_in[11];
    const float* b_comb = (const float*)d_in[12];
    const float* W_ih   = (const float*)d_in[13];
    const float* W_hh   = (const float*)d_in[14];
    const float* b_ih   = (const float*)d_in[15];
    const float* b_hh   = (const float*)d_in[16];
    float* outp = (float*)d_out;

    static bool attr_set = false;
    if (!attr_set) {
        cudaFuncSetAttribute(k_step, cudaFuncAttributeMaxDynamicSharedMemorySize, STEP_SMEM);
        attr_set = true;
    }

    // Parallel precompute (carry-independent); k_prep also resets dep flags
    k_prep<<<4096, 256>>>(D, W_gx, b_gx, W_feat, W_ih, W_hh, b_ih, b_hh,
                          W_gh, W_comb, W_hist);
    k_mma<M_GH>   <<<dim3(BTn / 64, HH / 128), 256>>>(Mm, D, b_gh);
    k_mma<M_ALPHA><<<dim3(BTn / 64, 1),        256>>>(Mm, D, b_comb);

    // Serial scan: ONE launch per step (stepA ∥ gates_partial; fin via dep flags)
    for (int t = 0; t < TT; t++) {
        k_step<<<544, 256, STEP_SMEM>>>(t, X, Mm, b_hist, b_feat, outp);
    }
    k_hT<<<(BB * HH) / 256, 256>>>(outp);
}

// round 16
// speedup vs baseline: 1.0030x; 1.0030x over previous
#include <cuda_runtime.h>
#include <cuda_bf16.h>
#include <math.h>
#include <stdint.h>

// ---------------- problem constants ----------------
#define BB 1024
#define TT 128
#define FF 128
#define HH 512
#define G4 2048            // 4*HH
#define KC 768             // 2*FF + HH
#define BTn (BB*TT)        // 131072

constexpr size_t BTFc    = (size_t)BTn * FF;
constexpr size_t OFF_IMP = 0;
constexpr size_t OFF_CH1 = BTFc;
constexpr size_t OFF_HT  = 2 * BTFc;
constexpr size_t OFF_XH  = 2 * BTFc + (size_t)BB * HH;
constexpr size_t OFF_CH2 = OFF_XH + BTFc;
constexpr size_t OFF_ZH  = OFF_CH2 + BTFc;

constexpr size_t ABUF = (size_t)BB * KC;   // one A-operand buffer (per parity)

// ---------------- device scratch (static, no allocs) ----------------
__device__ __align__(16) float g_gamma_x[(size_t)BTn * FF];   // 64 MB
__device__ __align__(16) float g_gamma_h[(size_t)BTn * HH];   // 256 MB
__device__ __align__(16) float g_alpha  [(size_t)BTn * FF];   // 64 MB
__device__ __align__(16) float g_h [BB * HH];
__device__ __align__(16) float g_c [BB * HH];
__device__ __align__(16) float g_bcat[G4];                    // gate-interleaved
__device__ __align__(16) float g_part[(size_t)BB * G4];       // 8 MB fp32 partial gates

// dependency flags (monotonic within a replay; reset by k_prep each replay)
__device__ unsigned g_fA[32];    // stepA block completion, value = t+1
__device__ unsigned g_fP[256];   // gates_partial block completion, value = t+1

// Gates A operand, bf16 split, DOUBLE-BUFFERED by step parity:
// buffer b = t&1 is read at step t; fin epilogue writes h*gamma(t+1) into 1-b.
// layout per row: [c_c(128) | m(128) | h*gamma_h(512)]
__device__ __align__(16) __nv_bfloat16 g_AH[2 * ABUF];
__device__ __align__(16) __nv_bfloat16 g_AL[2 * ABUF];

// bf16 split weights, TRANSPOSED [K][N] row-major (W_cat cols gate-interleaved n' = j*4+g)
__device__ __align__(16) __nv_bfloat16 g_WghH  [FF * HH],   g_WghL  [FF * HH];
__device__ __align__(16) __nv_bfloat16 g_WcombH[256 * FF],  g_WcombL[256 * FF];
__device__ __align__(16) __nv_bfloat16 g_WhistH[HH * FF],   g_WhistL[HH * FF];
__device__ __align__(16) __nv_bfloat16 g_WodH  [FF * FF],   g_WodL  [FF * FF];
__device__ __align__(16) __nv_bfloat16 g_WcatH[(size_t)KC * G4], g_WcatL[(size_t)KC * G4];

__device__ __forceinline__ float sigm(float x) { return 1.0f / (1.0f + expf(-x)); }

__device__ __forceinline__ void split_w(__nv_bfloat16* H, __nv_bfloat16* L, size_t i, float w) {
    __nv_bfloat16 h = __float2bfloat16(w);
    H[i] = h;
    L[i] = __float2bfloat16(w - __bfloat162float(h));
}

// ---------------- cp.async helpers ----------------
__device__ __forceinline__ void cp16(uint32_t dst, const void* src) {
    asm volatile("cp.async.cg.shared.global [%0], [%1], 16;" :: "r"(dst), "l"(src));
}
__device__ __forceinline__ void cp8(uint32_t dst, const void* src) {
    asm volatile("cp.async.ca.shared.global [%0], [%1], 8;" :: "r"(dst), "l"(src));
}
#define CP_COMMIT() asm volatile("cp.async.commit_group;" ::: "memory")
#define CP_WAIT(n)  asm volatile("cp.async.wait_group %0;" :: "n"(n) : "memory")

__device__ __forceinline__ void waitflag(const unsigned* f, unsigned want) {
    while (*(volatile const unsigned*)f < want) { __nanosleep(64); }
}

// ---------------- precompute ----------------
__global__ void k_prep(const float* __restrict__ D,    const float* __restrict__ Wgx,
                       const float* __restrict__ bgx,  const float* __restrict__ Wfeat,
                       const float* __restrict__ Wih,  const float* __restrict__ Whh,
                       const float* __restrict__ bih,  const float* __restrict__ bhh,
                       const float* __restrict__ Wgh,  const float* __restrict__ Wcomb,
                       const float* __restrict__ Whist)
{
    size_t tid    = (size_t)blockIdx.x * blockDim.x + threadIdx.x;
    size_t stride = (size_t)gridDim.x * blockDim.x;

    // reset dependency flags (required for CUDA-graph replays)
    for (size_t i = tid; i < 32;  i += stride) g_fA[i] = 0;
    for (size_t i = tid; i < 256; i += stride) g_fP[i] = 0;

    for (size_t i = tid; i < (size_t)BTn * FF; i += stride) {
        int f = (int)(i & (FF - 1));
        float v = D[i] * Wgx[f * FF + f] + bgx[f];
        g_gamma_x[i] = expf(-fmaxf(v, 0.0f));
    }
    // gate-interleaved bias: n' = j*4+g  <->  n = g*512+j
    for (size_t i = tid; i < (size_t)G4; i += stride) {
        int j = (int)(i >> 2), g = (int)(i & 3), n = g * HH + j;
        g_bcat[i] = bih[n] + bhh[n];
    }
    for (size_t i = tid; i < (size_t)BB * HH; i += stride) { g_h[i] = 0.0f; g_c[i] = 0.0f; }
    for (size_t i = tid; i < 2 * ABUF; i += stride) {
        g_AH[i] = __float2bfloat16(0.0f);
        g_AL[i] = __float2bfloat16(0.0f);
    }

    for (size_t i = tid; i < (size_t)FF * HH; i += stride) {     // W_gh^T  [K][N]
        int k = (int)(i / HH), n = (int)(i % HH);
        split_w(g_WghH, g_WghL, i, Wgh[(size_t)n * FF + k]);
    }
    for (size_t i = tid; i < (size_t)256 * FF; i += stride) {    // W_comb^T
        int k = (int)(i / FF), n = (int)(i % FF);
        split_w(g_WcombH, g_WcombL, i, Wcomb[(size_t)n * 256 + k]);
    }
    for (size_t i = tid; i < (size_t)HH * FF; i += stride) {     // W_hist^T
        int k = (int)(i / FF), n = (int)(i % FF);
        split_w(g_WhistH, g_WhistL, i, Whist[(size_t)n * HH + k]);
    }
    for (size_t i = tid; i < (size_t)FF * FF; i += stride) {     // W_feat^T off-diag
        int k = (int)(i / FF), n = (int)(i % FF);
        float w = (k == n) ? 0.0f : Wfeat[(size_t)n * FF + k];
        split_w(g_WodH, g_WodL, i, w);
    }
    // W_cat^T [K][N'], gate-interleaved columns
    for (size_t i = tid; i < (size_t)KC * G4; i += stride) {
        int k = (int)(i / G4), np = (int)(i % G4);
        int j = np >> 2, g = np & 3, n = g * HH + j;
        float w = (k < 2 * FF) ? Wih[(size_t)n * (2 * FF) + k]
                               : Whh[(size_t)n * HH + (k - 2 * FF)];
        split_w(g_WcatH, g_WcatL, i, w);
    }
}

// ---------------- mma.sync helpers ----------------
__device__ __forceinline__ void ldmA(uint32_t* r, const __nv_bfloat16* p) {
    uint32_t a = (uint32_t)__cvta_generic_to_shared(p);
    asm volatile("ldmatrix.sync.aligned.m8n8.x4.shared.b16 {%0,%1,%2,%3}, [%4];"
                 : "=r"(r[0]), "=r"(r[1]), "=r"(r[2]), "=r"(r[3]) : "r"(a));
}
__device__ __forceinline__ void ldmBT(uint32_t* r, const __nv_bfloat16* p) {
    uint32_t a = (uint32_t)__cvta_generic_to_shared(p);
    asm volatile("ldmatrix.sync.aligned.m8n8.x4.trans.shared.b16 {%0,%1,%2,%3}, [%4];"
                 : "=r"(r[0]), "=r"(r[1]), "=r"(r[2]), "=r"(r[3]) : "r"(a));
}
__device__ __forceinline__ void mma16816(float* d, const uint32_t* a, const uint32_t* b) {
    asm volatile("mma.sync.aligned.m16n8k16.row.col.f32.bf16.bf16.f32 "
                 "{%0,%1,%2,%3}, {%4,%5,%6,%7}, {%8,%9}, {%0,%1,%2,%3};"
                 : "+f"(d[0]), "+f"(d[1]), "+f"(d[2]), "+f"(d[3])
                 : "r"(a[0]), "r"(a[1]), "r"(a[2]), "r"(a[3]), "r"(b[0]), "r"(b[1]));
}
__device__ __forceinline__ void splitA_store(__nv_bfloat16* pH, __nv_bfloat16* pL, float4 a) {
    __nv_bfloat16 h0 = __float2bfloat16(a.x), h1 = __float2bfloat16(a.y);
    __nv_bfloat16 h2 = __float2bfloat16(a.z), h3 = __float2bfloat16(a.w);
    __nv_bfloat16 l0 = __float2bfloat16(a.x - __bfloat162float(h0));
    __nv_bfloat16 l1 = __float2bfloat16(a.y - __bfloat162float(h1));
    __nv_bfloat16 l2 = __float2bfloat16(a.z - __bfloat162float(h2));
    __nv_bfloat16 l3 = __float2bfloat16(a.w - __bfloat162float(h3));
    ((__nv_bfloat162*)pH)[0] = __halves2bfloat162(h0, h1);
    ((__nv_bfloat162*)pH)[1] = __halves2bfloat162(h2, h3);
    ((__nv_bfloat162*)pL)[0] = __halves2bfloat162(l0, l1);
    ((__nv_bfloat162*)pL)[1] = __halves2bfloat162(l2, l3);
}
__device__ __forceinline__ void split_scalar(__nv_bfloat16* pH, __nv_bfloat16* pL, float v) {
    __nv_bfloat16 h = __float2bfloat16(v);
    *pH = h;
    *pL = __float2bfloat16(v - __bfloat162float(h));
}

// ============================================================================
// Precompute GEMMs (parallel over B*T): GH and ALPHA (proven R5 code)
// ============================================================================
enum Mode { M_GH = 0, M_ALPHA = 1 };

template <int MODE>
__device__ __forceinline__ float4 loadApre(int row, int k, const float* __restrict__ Mm,
                                           const float* __restrict__ D)
{
    if (MODE == M_GH) {
        return *(const float4*)(D + (size_t)row * FF + k);
    } else {
        if (k < FF) return *(const float4*)(g_gamma_x + (size_t)row * FF + k);
        return *(const float4*)(Mm + (size_t)row * FF + (k - FF));
    }
}

template <int MODE>
__global__ __launch_bounds__(256)
void k_mma(const float* __restrict__ Mm, const float* __restrict__ D,
           const float* __restrict__ bias)
{
    constexpr int KD = (MODE == M_GH) ? FF : 2 * FF;
    constexpr int ND = (MODE == M_GH) ? HH : FF;
    constexpr int BM = 64, BN = 128;
    constexpr int LDA = 40, LDB = BN + 8;

    const __nv_bfloat16* WH = (MODE == M_GH) ? g_WghH : g_WcombH;
    const __nv_bfloat16* WL = (MODE == M_GH) ? g_WghL : g_WcombL;

    __shared__ __align__(16) __nv_bfloat16 AsH[BM * LDA], AsL[BM * LDA];
    __shared__ __align__(16) __nv_bfloat16 BsH[32 * LDB], BsL[32 * LDB];

    const int tid = threadIdx.x, lane = tid & 31, w = tid >> 5;
    const int wm = w >> 2, wn = w & 3;
    const int m0 = blockIdx.x * BM, n0 = blockIdx.y * BN;
    const int mA = tid >> 2, kA = (tid & 3) * 4;
    const int lr = lane & 15, lc = (lane >> 4) * 8;

    float acc[2][4][4];
    #pragma unroll
    for (int i = 0; i < 2; i++) for (int nb = 0; nb < 4; nb++) for (int e = 0; e < 4; e++)
        acc[i][nb][e] = 0.0f;

    for (int kt = 0; kt < KD; kt += 32) {
        float4 a1 = loadApre<MODE>(m0 + mA, kt + kA,      Mm, D);
        float4 a2 = loadApre<MODE>(m0 + mA, kt + kA + 16, Mm, D);
        uint4 bqh[2], bql[2];
        #pragma unroll
        for (int q = 0; q < 2; q++) {
            int cidx = q * 256 + tid;
            int row = cidx >> 4, col = (cidx & 15) * 8;
            size_t gi = (size_t)(kt + row) * ND + n0 + col;
            bqh[q] = *(const uint4*)(WH + gi);
            bql[q] = *(const uint4*)(WL + gi);
        }
        __syncthreads();
        splitA_store(&AsH[mA * LDA + kA],      &AsL[mA * LDA + kA],      a1);
        splitA_store(&AsH[mA * LDA + kA + 16], &AsL[mA * LDA + kA + 16], a2);
        #pragma unroll
        for (int q = 0; q < 2; q++) {
            int cidx = q * 256 + tid;
            int row = cidx >> 4, col = (cidx & 15) * 8;
            *(uint4*)&BsH[row * LDB + col] = bqh[q];
            *(uint4*)&BsL[row * LDB + col] = bql[q];
        }
        __syncthreads();
        #pragma unroll
        for (int kk = 0; kk < 32; kk += 16) {
            uint32_t ah[2][4], al[2][4];
            #pragma unroll
            for (int i = 0; i < 2; i++) {
                const int rowb = wm * 32 + i * 16 + lr;
                ldmA(ah[i], &AsH[rowb * LDA + kk + lc]);
                ldmA(al[i], &AsL[rowb * LDA + kk + lc]);
            }
            uint32_t bh[4][2], bl[4][2];
            #pragma unroll
            for (int g = 0; g < 2; g++) {
                uint32_t r4[4];
                const int coff = wn * 32 + g * 16 + lc;
                ldmBT(r4, &BsH[(kk + lr) * LDB + coff]);
                bh[2*g][0] = r4[0]; bh[2*g][1] = r4[1];
                bh[2*g+1][0] = r4[2]; bh[2*g+1][1] = r4[3];
                ldmBT(r4, &BsL[(kk + lr) * LDB + coff]);
                bl[2*g][0] = r4[0]; bl[2*g][1] = r4[1];
                bl[2*g+1][0] = r4[2]; bl[2*g+1][1] = r4[3];
            }
            #pragma unroll
            for (int i = 0; i < 2; i++)
                #pragma unroll
                for (int nb = 0; nb < 4; nb++) {
                    mma16816(acc[i][nb], ah[i], bh[nb]);
                    mma16816(acc[i][nb], al[i], bh[nb]);
                    mma16816(acc[i][nb], ah[i], bl[nb]);
                }
        }
    }
    #pragma unroll
    for (int i = 0; i < 2; i++)
        #pragma unroll
        for (int nb = 0; nb < 4; nb++) {
            const int rbase = m0 + wm * 32 + i * 16 + (lane >> 2);
            const int cbase = n0 + wn * 32 + nb * 8 + (lane & 3) * 2;
            #pragma unroll
            for (int e = 0; e < 4; e++) {
                const int r = rbase + (e >> 1) * 8;
                const int c = cbase + (e & 1);
                float v = acc[i][nb][e] + bias[c];
                if (MODE == M_GH) g_gamma_h[(size_t)r * HH + c] = expf(-fmaxf(v, 0.0f));
                else              g_alpha  [(size_t)r * FF + c] = sigm(v);
            }
        }
}

// ============================================================================
// Shared gates mainloop: 64x128 tile, 2-stage cp.async, K chunks of 32
// smem per stage (27648 bytes): AsH 5120 | AsL 5120 | BsH 8704 | BsL 8704
// ============================================================================
template <int KT0, int NCH>
__device__ __forceinline__ void gates_loop(char* sm, size_t ab, int m0, int n0,
                                           float (&acc)[2][4][4])
{
    const uint32_t smb = (uint32_t)__cvta_generic_to_shared(sm);
    constexpr int LDA = 40, LDB = 136, STG = 27648;
    const int tid = threadIdx.x, lane = tid & 31, w = tid >> 5;
    const int wm = w >> 2, wnq = w & 3;
    const int arow = tid >> 2, akq = (tid & 3) * 8;
    const int lr = lane & 15, lc = (lane >> 4) * 8;
    const int brow0 = tid >> 4, bcol0 = (tid & 15) * 8;
    const int brow1 = (256 + tid) >> 4;

    auto issueG = [&](int kt, int s) {
        const size_t ga = ab + (size_t)(m0 + arow) * KC + kt + akq;
        uint32_t base = smb + s * STG;
        uint32_t da = base + (arow * LDA + akq) * 2;
        cp16(da,        g_AH + ga);
        cp16(da + 5120, g_AL + ga);
        uint32_t bb = base + 10240;
        size_t gi0 = (size_t)(kt + brow0) * G4 + n0 + bcol0;
        size_t gi1 = (size_t)(kt + brow1) * G4 + n0 + bcol0;
        cp16(bb + (brow0 * LDB + bcol0) * 2,        g_WcatH + gi0);
        cp16(bb + (brow1 * LDB + bcol0) * 2,        g_WcatH + gi1);
        cp16(bb + 8704 + (brow0 * LDB + bcol0) * 2, g_WcatL + gi0);
        cp16(bb + 8704 + (brow1 * LDB + bcol0) * 2, g_WcatL + gi1);
    };

    issueG(KT0, 0); CP_COMMIT();

    #pragma unroll 1
    for (int c = 0; c < NCH; c++) {
        if (c + 1 < NCH) issueG(KT0 + (c + 1) * 32, (c + 1) & 1);
        CP_COMMIT();
        CP_WAIT(1);
        __syncthreads();
        const int s = c & 1;
        const __nv_bfloat16* AsH = (const __nv_bfloat16*)(sm + s * STG);
        const __nv_bfloat16* AsL = (const __nv_bfloat16*)(sm + s * STG + 5120);
        const __nv_bfloat16* BsH = (const __nv_bfloat16*)(sm + s * STG + 10240);
        const __nv_bfloat16* BsL = (const __nv_bfloat16*)(sm + s * STG + 18944);
        #pragma unroll
        for (int kk = 0; kk < 32; kk += 16) {
            uint32_t ah[2][4], al[2][4];
            #pragma unroll
            for (int i = 0; i < 2; i++) {
                const int rowb = wm * 32 + i * 16 + lr;
                ldmA(ah[i], &AsH[rowb * LDA + kk + lc]);
                ldmA(al[i], &AsL[rowb * LDA + kk + lc]);
            }
            uint32_t bh[4][2], bl[4][2];
            #pragma unroll
            for (int g = 0; g < 2; g++) {
                uint32_t r4[4];
                const int coff = wnq * 32 + g * 16 + lc;
                ldmBT(r4, &BsH[(kk + lr) * LDB + coff]);
                bh[2*g][0] = r4[0]; bh[2*g][1] = r4[1];
                bh[2*g+1][0] = r4[2]; bh[2*g+1][1] = r4[3];
                ldmBT(r4, &BsL[(kk + lr) * LDB + coff]);
                bl[2*g][0] = r4[0]; bl[2*g][1] = r4[1];
                bl[2*g+1][0] = r4[2]; bl[2*g+1][1] = r4[3];
            }
            #pragma unroll
            for (int i = 0; i < 2; i++)
                #pragma unroll
                for (int nb = 0; nb < 4; nb++) {
                    mma16816(acc[i][nb], ah[i], bh[nb]);
                    mma16816(acc[i][nb], al[i], bh[nb]);
                    mma16816(acc[i][nb], ah[i], bl[nb]);
                }
        }
        __syncthreads();
    }
}

// ============================================================================
// stepA body: fused XH (K=512, 3-stage) + ZH (K=128, 2-stage). BM=32.
// smem: A stages(3) s*5120 | B stages(3) 15360+s*17408 |
//       xcH 67584(8704) | xcL 76288(8704) | xhS 84992(16384) -> 101376
// ============================================================================
__device__ void stepA_body(int blk, int t, const float* __restrict__ X,
                           const float* __restrict__ Mm,
                           const float* __restrict__ bh_, const float* __restrict__ bf_,
                           float* __restrict__ outp, char* sm)
{
    const uint32_t smb = (uint32_t)__cvta_generic_to_shared(sm);
    __nv_bfloat16* xcH = (__nv_bfloat16*)(sm + 67584);
    __nv_bfloat16* xcL = (__nv_bfloat16*)(sm + 76288);
    float*         xhS = (float*)(sm + 84992);
    constexpr int LDA = 40, LDB = 136, LDX = 136;

    const size_t ab = (size_t)(t & 1) * ABUF;

    const int tid = threadIdx.x, lane = tid & 31, w = tid >> 5;
    const int wm = w >> 2, wn = w & 3;                 // 2x4 warps, warp tile 16x32
    const int m0 = blk * 32;
    const int arow = tid >> 3, akq = (tid & 7) * 4;
    const int lr = lane & 15, lc = (lane >> 4) * 8;
    const int brow0 = tid >> 4,          bcol0 = (tid & 15) * 8;
    const int brow1 = (256 + tid) >> 4;

    float acc[4][4];
    #pragma unroll
    for (int nb = 0; nb < 4; nb++) for (int e = 0; e < 4; e++) acc[nb][e] = 0.0f;

    auto issueXH = [&](int kt, int s) {
        const size_t ga = ab + (size_t)(m0 + arow) * KC + 256 + kt + akq;
        uint32_t da = smb + s * 5120 + (arow * LDA + akq) * 2;
        cp8(da,        g_AH + ga);
        cp8(da + 2560, g_AL + ga);
        uint32_t bb = smb + 15360 + s * 17408;
        size_t gi0 = (size_t)(kt + brow0) * FF + bcol0;
        size_t gi1 = (size_t)(kt + brow1) * FF + bcol0;
        cp16(bb + (brow0 * LDB + bcol0) * 2,        g_WhistH + gi0);
        cp16(bb + (brow1 * LDB + bcol0) * 2,        g_WhistH + gi1);
        cp16(bb + 8704 + (brow0 * LDB + bcol0) * 2, g_WhistL + gi0);
        cp16(bb + 8704 + (brow1 * LDB + bcol0) * 2, g_WhistL + gi1);
    };

    issueXH(0, 0);  CP_COMMIT();
    issueXH(32, 1); CP_COMMIT();

    #pragma unroll 1
    for (int c = 0; c < 16; c++) {
        if (c + 2 < 16) issueXH((c + 2) * 32, (c + 2) % 3);
        CP_COMMIT();
        CP_WAIT(2);
        __syncthreads();
        const int s = c % 3;
        const __nv_bfloat16* AsH = (const __nv_bfloat16*)(sm + s * 5120);
        const __nv_bfloat16* AsL = (const __nv_bfloat16*)(sm + s * 5120 + 2560);
        const __nv_bfloat16* BsH = (const __nv_bfloat16*)(sm + 15360 + s * 17408);
        const __nv_bfloat16* BsL = (const __nv_bfloat16*)(sm + 15360 + s * 17408 + 8704);
        #pragma unroll
        for (int kk = 0; kk < 32; kk += 16) {
            uint32_t ah[4], al[4];
            const int rowb = wm * 16 + lr;
            ldmA(ah, &AsH[rowb * LDA + kk + lc]);
            ldmA(al, &AsL[rowb * LDA + kk + lc]);
            uint32_t bh[4][2], bl[4][2];
            #pragma unroll
            for (int g = 0; g < 2; g++) {
                uint32_t r4[4];
                const int coff = wn * 32 + g * 16 + lc;
                ldmBT(r4, &BsH[(kk + lr) * LDB + coff]);
                bh[2*g][0] = r4[0]; bh[2*g][1] = r4[1];
                bh[2*g+1][0] = r4[2]; bh[2*g+1][1] = r4[3];
                ldmBT(r4, &BsL[(kk + lr) * LDB + coff]);
                bl[2*g][0] = r4[0]; bl[2*g][1] = r4[1];
                bl[2*g+1][0] = r4[2]; bl[2*g+1][1] = r4[3];
            }
            #pragma unroll
            for (int nb = 0; nb < 4; nb++) {
                mma16816(acc[nb], ah, bh[nb]);
                mma16816(acc[nb], al, bh[nb]);
                mma16816(acc[nb], ah, bl[nb]);
            }
        }
        __syncthreads();
    }

    // XH epilogue -> xh smem (fp32), xc smem (bf16 split), outp XH
    #pragma unroll
    for (int nb = 0; nb < 4; nb++) {
        const int rl0 = wm * 16 + (lane >> 2);
        const int c0  = wn * 32 + nb * 8 + (lane & 3) * 2;
        #pragma unroll
        for (int e = 0; e < 4; e++) {
            const int rl = rl0 + (e >> 1) * 8;
            const int c  = c0 + (e & 1);
            const int r  = m0 + rl;
            float v = acc[nb][e] + bh_[c];
            size_t idx = ((size_t)r * TT + t) * FF + c;
            outp[OFF_XH + idx] = v;
            xhS[rl * FF + c] = v;
            float mm = Mm[idx], xx = X[idx];
            float xc = mm * xx + (1.0f - mm) * v;
            split_scalar(&xcH[rl * LDX + c], &xcL[rl * LDX + c], xc);
        }
    }

    // ---- ZH: z_h = x_c @ Wod^T, K=128, 2-stage (B only) ----
    float accz[4][4];
    #pragma unroll
    for (int nb = 0; nb < 4; nb++) for (int e = 0; e < 4; e++) accz[nb][e] = 0.0f;

    auto issueZH = [&](int kt, int s) {
        uint32_t bb = smb + 15360 + s * 17408;
        size_t gi0 = (size_t)(kt + brow0) * FF + bcol0;
        size_t gi1 = (size_t)(kt + brow1) * FF + bcol0;
        cp16(bb + (brow0 * LDB + bcol0) * 2,        g_WodH + gi0);
        cp16(bb + (brow1 * LDB + bcol0) * 2,        g_WodH + gi1);
        cp16(bb + 8704 + (brow0 * LDB + bcol0) * 2, g_WodL + gi0);
        cp16(bb + 8704 + (brow1 * LDB + bcol0) * 2, g_WodL + gi1);
    };

    issueZH(0, 0); CP_COMMIT();

    #pragma unroll 1
    for (int c = 0; c < 4; c++) {
        if (c + 1 < 4) issueZH((c + 1) * 32, (c + 1) & 1);
        CP_COMMIT();
        CP_WAIT(1);
        __syncthreads();
        const int s = c & 1;
        const __nv_bfloat16* BsH = (const __nv_bfloat16*)(sm + 15360 + s * 17408);
        const __nv_bfloat16* BsL = (const __nv_bfloat16*)(sm + 15360 + s * 17408 + 8704);
        const int kt = c * 32;
        #pragma unroll
        for (int kk = 0; kk < 32; kk += 16) {
            uint32_t ah[4], al[4];
            const int rowb = wm * 16 + lr;
            ldmA(ah, &xcH[rowb * LDX + kt + kk + lc]);
            ldmA(al, &xcL[rowb * LDX + kt + kk + lc]);
            uint32_t bh[4][2], bl[4][2];
            #pragma unroll
            for (int g = 0; g < 2; g++) {
                uint32_t r4[4];
                const int coff = wn * 32 + g * 16 + lc;
                ldmBT(r4, &BsH[(kk + lr) * LDB + coff]);
                bh[2*g][0] = r4[0]; bh[2*g][1] = r4[1];
                bh[2*g+1][0] = r4[2]; bh[2*g+1][1] = r4[3];
                ldmBT(r4, &BsL[(kk + lr) * LDB + coff]);
                bl[2*g][0] = r4[0]; bl[2*g][1] = r4[1];
                bl[2*g+1][0] = r4[2]; bl[2*g+1][1] = r4[3];
            }
            #pragma unroll
            for (int nb = 0; nb < 4; nb++) {
                mma16816(accz[nb], ah, bh[nb]);
                mma16816(accz[nb], al, bh[nb]);
                mma16816(accz[nb], ah, bl[nb]);
            }
        }
        __syncthreads();
    }

    // ZH epilogue
    #pragma unroll
    for (int nb = 0; nb < 4; nb++) {
        const int rl0 = wm * 16 + (lane >> 2);
        const int c0  = wn * 32 + nb * 8 + (lane & 3) * 2;
        #pragma unroll
        for (int e = 0; e < 4; e++) {
            const int rl = rl0 + (e >> 1) * 8;
            const int c  = c0 + (e & 1);
            const int r  = m0 + rl;
            float v = accz[nb][e] + bf_[c];
            size_t idx = ((size_t)r * TT + t) * FF + c;
            float al2 = g_alpha[idx];
            float xh  = xhS[rl * FF + c];
            float ch  = al2 * v + (1.0f - al2) * xh;
            float mm  = Mm[idx], xx = X[idx];
            float cc  = mm * xx + (1.0f - mm) * ch;
            outp[OFF_ZH  + idx] = v;
            outp[OFF_CH1 + idx] = ch;
            outp[OFF_CH2 + idx] = ch;
            outp[OFF_IMP + idx] = cc;
            size_t abase = ab + (size_t)r * KC;
            split_scalar(&g_AH[abase + c], &g_AL[abase + c], cc);
            g_AH[abase + 128 + c] = __float2bfloat16(mm);
            g_AL[abase + 128 + c] = __float2bfloat16(0.0f);
        }
    }
}

// ============================================================================
// k_step: ONE launch per timestep, grid 544.
//   blocks [0,32):    stepA (BM=32)                -> flags g_fA
//   blocks [32,288):  gates_partial (K=[256,768))  -> flags g_fP
//   blocks [288,544): fin (K=[0,256) + partial + bias + LSTM); waits on flags.
// Deadlock-free: producers (lower bids) never wait; scheduler issues bids in
// order so producers always occupy slots before later fin bids.
// fin A-tile loads use cp.async.cg (L1-bypass) -> coherent with producer fences.
// ============================================================================
#define STEP_SMEM 101376

__global__ __launch_bounds__(256, 2)
void k_step(int t, const float* __restrict__ X, const float* __restrict__ Mm,
            const float* __restrict__ bh_, const float* __restrict__ bf_,
            float* __restrict__ outp)
{
    extern __shared__ __align__(16) char sm[];
    const int bid = blockIdx.x;
    const int tid = threadIdx.x;
    const size_t ab = (size_t)(t & 1) * ABUF;

    if (bid < 32) {
        // ---- role: stepA ----
        stepA_body(bid, t, X, Mm, bh_, bf_, outp, sm);
        __threadfence();
        __syncthreads();
        if (tid == 0) atomicExch(&g_fA[bid], (unsigned)(t + 1));
        return;
    }

    if (bid < 288) {
        // ---- role: gates_partial, K = [256,768) ----
        const int gb = bid - 32;
        const int m0 = (gb >> 4) * 64, n0 = (gb & 15) * 128;
        const int lane = tid & 31, w = tid >> 5;
        const int wm = w >> 2, wnq = w & 3;

        float acc[2][4][4];
        #pragma unroll
        for (int i = 0; i < 2; i++) for (int nb = 0; nb < 4; nb++) for (int e = 0; e < 4; e++)
            acc[i][nb][e] = 0.0f;

        gates_loop<256, 16>(sm, ab, m0, n0, acc);

        #pragma unroll
        for (int i = 0; i < 2; i++)
            #pragma unroll
            for (int nb = 0; nb < 4; nb++) {
                const int rl0 = wm * 32 + i * 16 + (lane >> 2);
                const int cl0 = wnq * 32 + nb * 8 + (lane & 3) * 2;
                #pragma unroll
                for (int e = 0; e < 4; e++) {
                    const int r  = m0 + rl0 + (e >> 1) * 8;
                    const int cl = cl0 + (e & 1);
                    g_part[(size_t)r * G4 + n0 + cl] = acc[i][nb][e];
                }
            }
        __threadfence();
        __syncthreads();
        if (tid == 0) atomicExch(&g_fP[gb], (unsigned)(t + 1));
        return;
    }

    // ---- role: fin ----
    const int fb = bid - 288;
    const int bx = fb >> 4, by = fb & 15;
    const int m0 = bx * 64, n0 = by * 128;
    const size_t aw = (size_t)((t + 1) & 1) * ABUF;

    if (tid == 0) {
        const unsigned want = (unsigned)(t + 1);
        waitflag(&g_fA[2 * bx],     want);
        waitflag(&g_fA[2 * bx + 1], want);
        waitflag(&g_fP[fb],         want);
    }
    __syncthreads();
    __threadfence();   // acquire-ish: order subsequent reads after flag observation

    float* sg = (float*)sm;
    constexpr int LDS_G = 132;
    const int lane = tid & 31, w = tid >> 5;
    const int wm = w >> 2, wnq = w & 3;

    float acc[2][4][4];
    #pragma unroll
    for (int i = 0; i < 2; i++) for (int nb = 0; nb < 4; nb++) for (int e = 0; e < 4; e++)
        acc[i][nb][e] = 0.0f;

    gates_loop<0, 8>(sm, ab, m0, n0, acc);

    // add partial + bias, stage into smem overlay
    #pragma unroll
    for (int i = 0; i < 2; i++)
        #pragma unroll
        for (int nb = 0; nb < 4; nb++) {
            const int rl0 = wm * 32 + i * 16 + (lane >> 2);
            const int cl0 = wnq * 32 + nb * 8 + (lane & 3) * 2;
            #pragma unroll
            for (int e = 0; e < 4; e++) {
                const int rl = rl0 + (e >> 1) * 8;
                const int cl = cl0 + (e & 1);
                sg[rl * LDS_G + cl] = acc[i][nb][e]
                                    + g_part[(size_t)(m0 + rl) * G4 + n0 + cl]
                                    + g_bcat[n0 + cl];
            }
        }
    __syncthreads();

    // fused LSTM update: tile owns rows [m0,m0+64) x j in [n0/4, n0/4+32)
    const int j0 = n0 >> 2;
    for (int idx = tid; idx < 64 * 32; idx += 256) {
        const int rl = idx >> 5, jj = idx & 31;
        const float* gb2 = sg + rl * LDS_G + jj * 4;
        float ig = sigm(gb2[0]);
        float fg = sigm(gb2[1]);
        float gg = tanhf(gb2[2]);
        float og = sigm(gb2[3]);
        const int r = m0 + rl, j = j0 + jj;
        size_t hi = (size_t)r * HH + j;
        float cnew = fg * g_c[hi] + ig * gg;
        g_c[hi] = cnew;
        float hnew = og * tanhf(cnew);
        g_h[hi] = hnew;
        if (t + 1 < TT) {
            float gam = g_gamma_h[((size_t)r * TT + t + 1) * HH + j];
            split_scalar(&g_AH[aw + (size_t)r * KC + 256 + j],
                         &g_AL[aw + (size_t)r * KC + 256 + j], hnew * gam);
        }
    }
}

__global__ void k_hT(float* __restrict__ outp)
{
    int i = blockIdx.x * blockDim.x + threadIdx.x;
    if (i < BB * HH) outp[OFF_HT + i] = g_h[i];
}

// ---------------- launch ----------------
extern "C" void kernel_launch(void* const* d_in, const int* in_sizes, int n_in,
                              void* d_out, int out_size)
{
    const float* X      = (const float*)d_in[0];
    const float* Mm     = (const float*)d_in[1];
    const float* D      = (const float*)d_in[2];
    const float* W_gh   = (const float*)d_in[3];
    const float* b_gh   = (const float*)d_in[4];
    const float* W_gx   = (const float*)d_in[5];
    const float* b_gx   = (const float*)d_in[6];
    const float* W_hist = (const float*)d_in[7];
    const float* b_hist = (const float*)d_in[8];
    const float* W_feat = (const float*)d_in[9];
    const float* b_feat = (const float*)d_in[10];
    const float* W_comb = (const float*)d_in[11];
    const float* b_comb = (const float*)d_in[12];
    const float* W_ih   = (const float*)d_in[13];
    const float* W_hh   = (const float*)d_in[14];
    const float* b_ih   = (const float*)d_in[15];
    const float* b_hh   = (const float*)d_in[16];
    float* outp = (float*)d_out;

    static bool attr_set = false;
    if (!attr_set) {
        cudaFuncSetAttribute(k_step, cudaFuncAttributeMaxDynamicSharedMemorySize, STEP_SMEM);
        attr_set = true;
    }

    // Parallel precompute (carry-independent); k_prep also resets dep flags
    k_prep<<<4096, 256>>>(D, W_gx, b_gx, W_feat, W_ih, W_hh, b_ih, b_hh,
                          W_gh, W_comb, W_hist);
    k_mma<M_GH>   <<<dim3(BTn / 64, HH / 128), 256>>>(Mm, D, b_gh);
    k_mma<M_ALPHA><<<dim3(BTn / 64, 1),        256>>>(Mm, D, b_comb);

    // Serial scan: ONE launch per step (stepA ∥ gates_partial; fin via dep flags)
    for (int t = 0; t < TT; t++) {
        k_step<<<544, 256, STEP_SMEM>>>(t, X, Mm, b_hist, b_feat, outp);
    }
    k_hT<<<(BB * HH) / 256, 256>>>(outp);
}